// round 1
// baseline (speedup 1.0000x reference)
#include <cuda_runtime.h>

namespace {

constexpr int NDIG  = 9;
constexpr int NCELL = 81;
constexpr int HID   = 128;

__global__ __launch_bounds__(128)
void sudoku_kernel(const float* __restrict__ x,
                   const float* __restrict__ W1,
                   const float* __restrict__ W2,
                   float* __restrict__ out)
{
    __shared__ float W1t[27][HID];          // transposed: W1t[k][j]
    __shared__ float W2s[NDIG][HID];
    __shared__ float cnt[3][9][9];          // digit counts per (type, group)
    __shared__ float xp[NCELL][NDIG];       // running x_pred
    __shared__ float score_s[NCELL];        // 0 for non-empty cells
    __shared__ int   pos_s[NCELL];
    __shared__ unsigned char emptyb[NCELL];
    __shared__ unsigned long long warpmax[4];
    __shared__ int sel_m;
    __shared__ int done_s;

    const int tid  = threadIdx.x;
    const int lane = tid & 31;
    const int wid  = tid >> 5;
    const long long b = blockIdx.x;
    const float* xb = x + b * (NCELL * NDIG);

    // Stage weights
    for (int i = tid; i < HID * 27; i += 128) {
        int j = i / 27, k = i % 27;
        W1t[k][j] = W1[i];
    }
    for (int i = tid; i < NDIG * HID; i += 128)
        (&W2s[0][0])[i] = W2[i];
    for (int i = tid; i < 3 * 9 * 9; i += 128)
        (&cnt[0][0][0])[i] = 0.0f;
    __syncthreads();

    // Per-cell init: copy x into xp, detect given digit, accumulate counts
    if (tid < NCELL) {
        int d = -1;
        #pragma unroll
        for (int e = 0; e < 9; e++) {
            float v = xb[tid * 9 + e];
            xp[tid][e] = v;
            if (v > 0.5f) d = e;
        }
        score_s[tid] = 0.0f;
        pos_s[tid]   = 0;
        if (d >= 0) {
            emptyb[tid] = 0;
            int r = tid / 9, c = tid % 9, bx = (r / 3) * 3 + c / 3;
            atomicAdd(&cnt[0][r][d],  1.0f);
            atomicAdd(&cnt[1][c][d],  1.0f);
            atomicAdd(&cnt[2][bx][d], 1.0f);
        } else {
            emptyb[tid] = 1;
        }
    }
    __syncthreads();

    // Warp-collective: recompute h/y/softmax/score/x_pred for one cell.
    // Cell c reads constraint type r=c/27, groups of q = 3*(c%27)+{0,1,2}.
    auto compute_cell = [&](int c) {
        const int r  = c / 27;
        const int q0 = 3 * (c % 27);
        int g0, g1, g2;
        if (r == 0)      { g0 = g1 = g2 = q0 / 9; }
        else if (r == 1) { g0 = q0 % 9; g1 = g0 + 1; g2 = g0 + 2; }
        else             { g0 = g1 = g2 = 3 * (q0 / 27) + (q0 % 9) / 3; }

        const float* cp0 = &cnt[r][g0][0];
        const float* cp1 = &cnt[r][g1][0];
        const float* cp2 = &cnt[r][g2][0];

        float h0 = 0.f, h1 = 0.f, h2 = 0.f, h3 = 0.f;
        #pragma unroll
        for (int e = 0; e < 9; e++) {
            float fv = cp0[e];
            h0 = fmaf(fv, W1t[e][lane     ], h0);
            h1 = fmaf(fv, W1t[e][lane + 32], h1);
            h2 = fmaf(fv, W1t[e][lane + 64], h2);
            h3 = fmaf(fv, W1t[e][lane + 96], h3);
        }
        #pragma unroll
        for (int e = 0; e < 9; e++) {
            float fv = cp1[e];
            h0 = fmaf(fv, W1t[9 + e][lane     ], h0);
            h1 = fmaf(fv, W1t[9 + e][lane + 32], h1);
            h2 = fmaf(fv, W1t[9 + e][lane + 64], h2);
            h3 = fmaf(fv, W1t[9 + e][lane + 96], h3);
        }
        #pragma unroll
        for (int e = 0; e < 9; e++) {
            float fv = cp2[e];
            h0 = fmaf(fv, W1t[18 + e][lane     ], h0);
            h1 = fmaf(fv, W1t[18 + e][lane + 32], h1);
            h2 = fmaf(fv, W1t[18 + e][lane + 64], h2);
            h3 = fmaf(fv, W1t[18 + e][lane + 96], h3);
        }
        h0 = fmaxf(h0, 0.f); h1 = fmaxf(h1, 0.f);
        h2 = fmaxf(h2, 0.f); h3 = fmaxf(h3, 0.f);

        float p[9];
        #pragma unroll
        for (int e = 0; e < 9; e++) {
            float acc = h0 * W2s[e][lane];
            acc = fmaf(h1, W2s[e][lane + 32], acc);
            acc = fmaf(h2, W2s[e][lane + 64], acc);
            acc = fmaf(h3, W2s[e][lane + 96], acc);
            p[e] = acc;
        }
        #pragma unroll
        for (int off = 16; off > 0; off >>= 1) {
            #pragma unroll
            for (int e = 0; e < 9; e++)
                p[e] += __shfl_xor_sync(0xffffffffu, p[e], off);
        }
        if (lane == 0) {
            float mx = p[0];
            #pragma unroll
            for (int e = 1; e < 9; e++) mx = fmaxf(mx, p[e]);
            float s[9], sum = 0.f;
            #pragma unroll
            for (int e = 0; e < 9; e++) { s[e] = expf(p[e] - mx); sum += s[e]; }
            float best = -1.f; int bp = 0;
            #pragma unroll
            for (int e = 0; e < 9; e++) {
                float v = s[e] / sum;
                xp[c][e] = v;
                if (v > best) { best = v; bp = e; }
            }
            score_s[c] = best;
            pos_s[c]   = bp;
        }
    };

    // Step 0: full pass over all empty cells (warp-per-cell, strided)
    for (int c = wid; c < NCELL; c += 4)
        if (emptyb[c]) compute_cell(c);

    // Sequential fill loop; each iteration recomputes only the 15 affected cells
    for (int iter = 0; iter < NCELL; ++iter) {
        __syncthreads();

        // block argmax over scores: higher score wins, tie -> lowest index
        float sc = (tid < NCELL) ? score_s[tid] : 0.0f;
        unsigned long long key = 0ull;
        if (sc > 0.0f)
            key = (((unsigned long long)__float_as_uint(sc)) << 32)
                | (unsigned long long)(127 - tid);
        #pragma unroll
        for (int off = 16; off > 0; off >>= 1) {
            unsigned long long o = __shfl_xor_sync(0xffffffffu, key, off);
            if (o > key) key = o;
        }
        if (lane == 0) warpmax[wid] = key;
        __syncthreads();

        if (tid == 0) {
            unsigned long long k = warpmax[0];
            if (warpmax[1] > k) k = warpmax[1];
            if (warpmax[2] > k) k = warpmax[2];
            if (warpmax[3] > k) k = warpmax[3];
            if (k == 0ull) {
                done_s = 1;                 // no empty cells remain
            } else {
                done_s = 0;
                int m = 127 - (int)(k & 0xFFFFFFFFull);
                int d = pos_s[m];
                sel_m = m;
                int rm = m / 9, cm = m % 9, bm = (rm / 3) * 3 + cm / 3;
                cnt[0][rm][d] += 1.0f;
                cnt[1][cm][d] += 1.0f;
                cnt[2][bm][d] += 1.0f;
                emptyb[m]  = 0;
                score_s[m] = 0.0f;
            }
        }
        __syncthreads();
        if (done_s) break;

        const int m   = sel_m;
        const int rm  = m / 9, cm = m % 9;
        const int cm3 = cm / 3, brm = (rm / 3) * 3;

        // 15 affected cells: 3 row-consumers, 9 col-consumers, 3 box-consumers
        for (int i = wid; i < 15; i += 4) {
            int c;
            if (i < 3)       c = 3 * rm + i;
            else if (i < 12) c = 27 + 3 * (i - 3) + cm3;
            else             c = 54 + 3 * (brm + (i - 12)) + cm3;
            if (emptyb[c]) compute_cell(c);
        }
    }
    __syncthreads();

    const float* xpf = &xp[0][0];
    float* ob = out + b * (NCELL * NDIG);
    for (int i = tid; i < NCELL * NDIG; i += 128)
        ob[i] = xpf[i];
}

} // namespace

extern "C" void kernel_launch(void* const* d_in, const int* in_sizes, int n_in,
                              void* d_out, int out_size) {
    const float* x  = (const float*)d_in[0];
    const float* W1 = (const float*)d_in[1];
    const float* W2 = (const float*)d_in[2];
    // d_in[3] = constraint_mask: unused, its structure is reproduced analytically
    float* out = (float*)d_out;
    int B = in_sizes[0] / (81 * 9);
    sudoku_kernel<<<B, 128>>>(x, W1, W2, out);
}

// round 2
// speedup vs baseline: 1.0636x; 1.0636x over previous
#include <cuda_runtime.h>

namespace {

constexpr int HID = 128;
// dynamic smem: W1t[27][128] | Wsum[9][128] | zs[81][128] | xp[81*9]
constexpr int DYN_FLOATS = (27 + 9 + 81) * HID + 81 * 9;
constexpr int DYN_BYTES  = DYN_FLOATS * 4;

__global__ __launch_bounds__(128)
void sudoku_kernel(const float* __restrict__ x,
                   const float* __restrict__ W1,
                   const float* __restrict__ W2,
                   float* __restrict__ out)
{
    extern __shared__ float dyn[];
    float* W1t  = dyn;                    // [27][HID]  W1 transposed
    float* Wsum = dyn + 27 * HID;         // [9][HID]   W1t[d]+W1t[9+d]+W1t[18+d]
    float* zs   = dyn + 36 * HID;         // [81][HID]  cached pre-activations
    float* xp   = dyn + 117 * HID;        // [81][9]    running x_pred

    __shared__ float cnt[3][9][9];
    __shared__ float score_s[81];
    __shared__ int   pos_s[81];
    __shared__ unsigned char emptyb[81];
    __shared__ unsigned long long warpmax[4];
    __shared__ int sel_m, sel_d, done_s;

    const int tid  = threadIdx.x;
    const int lane = tid & 31;
    const int wid  = tid >> 5;
    const long long b = blockIdx.x;
    const float* xb = x + b * 729;

    // W2 resident in registers: w2r[e*4+s] = W2[e][lane+32*s]
    float w2r[36];
    #pragma unroll
    for (int e = 0; e < 9; e++)
        #pragma unroll
        for (int s = 0; s < 4; s++)
            w2r[e * 4 + s] = W2[e * HID + lane + 32 * s];

    // Stage W1 transposed; zero counts
    for (int i = tid; i < 27 * HID; i += 128) {
        int j = i / 27, k = i % 27;
        W1t[k * HID + j] = W1[i];
    }
    for (int i = tid; i < 243; i += 128) (&cnt[0][0][0])[i] = 0.0f;
    __syncthreads();

    // Wsum rows; xp init; per-cell given-digit detection + count accumulation
    for (int i = tid; i < 9 * HID; i += 128)
        Wsum[i] = W1t[i] + W1t[9 * HID + i] + W1t[18 * HID + i];
    for (int i = tid; i < 729; i += 128) xp[i] = xb[i];
    if (tid < 81) {
        int d = -1;
        #pragma unroll
        for (int e = 0; e < 9; e++)
            if (xb[tid * 9 + e] > 0.5f) d = e;
        score_s[tid] = 0.0f;
        pos_s[tid]   = 0;
        if (d >= 0) {
            emptyb[tid] = 0;
            int r = tid / 9, c = tid % 9, bx = (r / 3) * 3 + c / 3;
            atomicAdd(&cnt[0][r][d],  1.0f);
            atomicAdd(&cnt[1][c][d],  1.0f);
            atomicAdd(&cnt[2][bx][d], 1.0f);
        } else {
            emptyb[tid] = 1;
        }
    }
    __syncthreads();

    // relu(z) @ W2^T, warp reduce, softmax + score/pos/x_pred update (lane 0)
    auto compute_y = [&](int c, float z0, float z1, float z2, float z3) {
        float h0 = fmaxf(z0, 0.f), h1 = fmaxf(z1, 0.f);
        float h2 = fmaxf(z2, 0.f), h3 = fmaxf(z3, 0.f);
        float p[9];
        #pragma unroll
        for (int e = 0; e < 9; e++) {
            float a = h0 * w2r[e * 4 + 0];
            a = fmaf(h1, w2r[e * 4 + 1], a);
            a = fmaf(h2, w2r[e * 4 + 2], a);
            a = fmaf(h3, w2r[e * 4 + 3], a);
            p[e] = a;
        }
        #pragma unroll
        for (int off = 16; off > 0; off >>= 1) {
            #pragma unroll
            for (int e = 0; e < 9; e++)
                p[e] += __shfl_xor_sync(0xffffffffu, p[e], off);
        }
        if (lane == 0) {
            float mx = p[0];
            #pragma unroll
            for (int e = 1; e < 9; e++) mx = fmaxf(mx, p[e]);
            float s[9], sum = 0.f;
            #pragma unroll
            for (int e = 0; e < 9; e++) { s[e] = expf(p[e] - mx); sum += s[e]; }
            float best = -1.f; int bp = 0;
            #pragma unroll
            for (int e = 0; e < 9; e++) {
                float v = s[e] / sum;
                xp[c * 9 + e] = v;
                if (v > best) { best = v; bp = e; }
            }
            score_s[c] = best;
            pos_s[c]   = bp;
        }
    };

    // Initial full pass: build z for every empty cell, cache it, compute y.
    for (int c = wid; c < 81; c += 4) {
        if (!emptyb[c]) continue;
        float z0 = 0.f, z1 = 0.f, z2 = 0.f, z3 = 0.f;
        if (c < 27) {                 // row consumer: f 3x-replicated -> Wsum
            const float* cp = &cnt[0][c / 3][0];
            #pragma unroll
            for (int e = 0; e < 9; e++) {
                float fv = cp[e];
                const float* w = &Wsum[e * HID + lane];
                z0 = fmaf(fv, w[0],  z0);
                z1 = fmaf(fv, w[32], z1);
                z2 = fmaf(fv, w[64], z2);
                z3 = fmaf(fv, w[96], z3);
            }
        } else if (c < 54) {          // column consumer: 3 distinct groups
            int g0 = 3 * ((c - 27) % 3);
            #pragma unroll
            for (int blk = 0; blk < 3; blk++) {
                const float* cp = &cnt[1][g0 + blk][0];
                #pragma unroll
                for (int e = 0; e < 9; e++) {
                    float fv = cp[e];
                    const float* w = &W1t[(9 * blk + e) * HID + lane];
                    z0 = fmaf(fv, w[0],  z0);
                    z1 = fmaf(fv, w[32], z1);
                    z2 = fmaf(fv, w[64], z2);
                    z3 = fmaf(fv, w[96], z3);
                }
            }
        } else {                      // box consumer: f 3x-replicated -> Wsum
            int cc = c - 54;
            const float* cp = &cnt[2][3 * (cc / 9) + (cc % 3)][0];
            #pragma unroll
            for (int e = 0; e < 9; e++) {
                float fv = cp[e];
                const float* w = &Wsum[e * HID + lane];
                z0 = fmaf(fv, w[0],  z0);
                z1 = fmaf(fv, w[32], z1);
                z2 = fmaf(fv, w[64], z2);
                z3 = fmaf(fv, w[96], z3);
            }
        }
        float* zp = &zs[c * HID + lane];
        zp[0] = z0; zp[32] = z1; zp[64] = z2; zp[96] = z3;
        compute_y(c, z0, z1, z2, z3);
    }

    // Sequential fill loop: incremental z update on the 15 affected cells.
    for (int iter = 0; iter < 81; ++iter) {
        __syncthreads();

        // block argmax (first-max tie-break via 127-tid)
        float sc = (tid < 81) ? score_s[tid] : 0.0f;
        unsigned long long key = 0ull;
        if (sc > 0.0f)
            key = (((unsigned long long)__float_as_uint(sc)) << 32)
                | (unsigned long long)(127 - tid);
        #pragma unroll
        for (int off = 16; off > 0; off >>= 1) {
            unsigned long long o = __shfl_xor_sync(0xffffffffu, key, off);
            if (o > key) key = o;
        }
        if (lane == 0) warpmax[wid] = key;
        __syncthreads();

        if (tid == 0) {
            unsigned long long k = warpmax[0];
            if (warpmax[1] > k) k = warpmax[1];
            if (warpmax[2] > k) k = warpmax[2];
            if (warpmax[3] > k) k = warpmax[3];
            if (k == 0ull) {
                done_s = 1;
            } else {
                done_s = 0;
                int m = 127 - (int)(k & 0xFFFFFFFFull);
                int d = pos_s[m];
                sel_m = m; sel_d = d;
                int rm = m / 9, cm = m % 9, bm = (rm / 3) * 3 + cm / 3;
                cnt[0][rm][d] += 1.0f;
                cnt[1][cm][d] += 1.0f;
                cnt[2][bm][d] += 1.0f;
                emptyb[m]  = 0;
                score_s[m] = 0.0f;
            }
        }
        __syncthreads();
        if (done_s) break;

        const int m   = sel_m, d = sel_d;
        const int rm  = m / 9, cm = m % 9;
        const int cm3 = cm / 3, brm = (rm / 3) * 3;

        // 3 row-consumers, 9 col-consumers, 3 box-consumers
        for (int i = wid; i < 15; i += 4) {
            int c; bool iscol;
            if (i < 3)       { c = 3 * rm + i;                  iscol = false; }
            else if (i < 12) { c = 27 + 3 * (i - 3) + cm3;      iscol = true;  }
            else             { c = 54 + 3 * (brm + (i - 12)) + cm3; iscol = false; }
            if (!emptyb[c]) continue;
            const float* w = iscol ? &W1t[(9 * (cm % 3) + d) * HID + lane]
                                   : &Wsum[d * HID + lane];
            float* zp = &zs[c * HID + lane];
            float z0 = zp[0]  + w[0];
            float z1 = zp[32] + w[32];
            float z2 = zp[64] + w[64];
            float z3 = zp[96] + w[96];
            zp[0] = z0; zp[32] = z1; zp[64] = z2; zp[96] = z3;
            compute_y(c, z0, z1, z2, z3);
        }
    }
    __syncthreads();

    float* ob = out + b * 729;
    for (int i = tid; i < 729; i += 128) ob[i] = xp[i];
}

} // namespace

extern "C" void kernel_launch(void* const* d_in, const int* in_sizes, int n_in,
                              void* d_out, int out_size) {
    const float* x  = (const float*)d_in[0];
    const float* W1 = (const float*)d_in[1];
    const float* W2 = (const float*)d_in[2];
    float* out = (float*)d_out;
    int B = in_sizes[0] / 729;
    cudaFuncSetAttribute(sudoku_kernel,
                         cudaFuncAttributeMaxDynamicSharedMemorySize, DYN_BYTES);
    sudoku_kernel<<<B, 128, DYN_BYTES>>>(x, W1, W2, out);
}

// round 4
// speedup vs baseline: 1.5991x; 1.5035x over previous
#include <cuda_runtime.h>

namespace {

constexpr int THREADS = 160;   // 5 warps

__device__ __align__(16) float g_W1p[27 * 128];  // W1 transposed: [k][j]
__device__ __align__(16) float g_Wsum[9 * 128];  // W1p[d]+W1p[9+d]+W1p[18+d]

__global__ void prep_kernel(const float* __restrict__ W1) {
    int j = threadIdx.x;  // 0..127
    #pragma unroll
    for (int k = 0; k < 27; k++) g_W1p[k * 128 + j] = W1[j * 27 + k];
    #pragma unroll
    for (int d = 0; d < 9; d++)
        g_Wsum[d * 128 + j] = W1[j * 27 + d] + W1[j * 27 + 9 + d] + W1[j * 27 + 18 + d];
}

// Integer redux IS supported on sm_103 (sm_80+ feature); f32 redux is not.
__device__ __forceinline__ unsigned redux_maxu(unsigned v) {
    unsigned r; asm("redux.sync.max.u32 %0, %1, 0xffffffff;" : "=r"(r) : "r"(v)); return r;
}
__device__ __forceinline__ unsigned redux_minu(unsigned v) {
    unsigned r; asm("redux.sync.min.u32 %0, %1, 0xffffffff;" : "=r"(r) : "r"(v)); return r;
}

__global__ __launch_bounds__(THREADS, 5)
void sudoku_kernel(const float* __restrict__ x,
                   const float* __restrict__ W2,
                   float* __restrict__ out)
{
    __shared__ __align__(16) float zs[81 * 128];  // cached pre-activations (float4/lane)
    __shared__ float cnt[3][9][9];
    __shared__ float score_s[96];                 // 81 used; padded reads return 0
    __shared__ int   pos_s[81];
    __shared__ unsigned char emptyb[81];

    const int tid  = threadIdx.x;
    const int lane = tid & 31;
    const int wid  = tid >> 5;
    const long long b = blockIdx.x;
    const float* xb = x + b * 729;
    float* ob = out + b * 729;

    // W2 in registers: lane owns hidden units 4*lane .. 4*lane+3
    float4 w2r[9];
    #pragma unroll
    for (int e = 0; e < 9; e++)
        w2r[e] = __ldg((const float4*)(W2 + e * 128) + lane);

    for (int i = tid; i < 243; i += THREADS) (&cnt[0][0][0])[i] = 0.f;
    for (int i = tid; i < 729; i += THREADS) ob[i] = xb[i];   // x_pred init = x
    if (tid < 96) score_s[tid] = 0.f;
    __syncthreads();

    if (tid < 81) {
        int d = -1;
        #pragma unroll
        for (int e = 0; e < 9; e++)
            if (xb[tid * 9 + e] > 0.5f) d = e;
        pos_s[tid] = 0;
        if (d >= 0) {
            emptyb[tid] = 0;
            int r = tid / 9, c = tid % 9, bx = (r / 3) * 3 + c / 3;
            atomicAdd(&cnt[0][r][d],  1.f);
            atomicAdd(&cnt[1][c][d],  1.f);
            atomicAdd(&cnt[2][bx][d], 1.f);
        } else {
            emptyb[tid] = 1;
        }
    }
    __syncthreads();

    // relu(z) @ W2^T via XOR butterfly (all lanes get full y), then fully
    // redundant per-lane softmax — no cross-lane ops after the butterfly.
    auto compute_y = [&](int c, float4 z) {
        float h0 = fmaxf(z.x, 0.f), h1 = fmaxf(z.y, 0.f);
        float h2 = fmaxf(z.z, 0.f), h3 = fmaxf(z.w, 0.f);
        float p[9];
        #pragma unroll
        for (int e = 0; e < 9; e++) {
            float a = h0 * w2r[e].x;
            a = fmaf(h1, w2r[e].y, a);
            a = fmaf(h2, w2r[e].z, a);
            a = fmaf(h3, w2r[e].w, a);
            p[e] = a;
        }
        #pragma unroll
        for (int off = 16; off > 0; off >>= 1) {
            #pragma unroll
            for (int e = 0; e < 9; e++)
                p[e] += __shfl_xor_sync(0xffffffffu, p[e], off);
        }
        float mx = p[0];
        #pragma unroll
        for (int e = 1; e < 9; e++) mx = fmaxf(mx, p[e]);
        float q[9], sum = 0.f;
        #pragma unroll
        for (int e = 0; e < 9; e++) { q[e] = expf(p[e] - mx); sum += q[e]; }
        float best = q[0]; int bp = 0;
        #pragma unroll
        for (int e = 1; e < 9; e++)
            if (q[e] > best) { best = q[e]; bp = e; }   // strict > = first max
        if (lane < 9) ob[c * 9 + lane] = q[lane] / sum;
        if (lane == 0) { score_s[c] = best / sum; pos_s[c] = bp; }
    };

    // Initial full pass: fresh z for every empty cell
    for (int c = wid; c < 81; c += 5) {
        if (!emptyb[c]) continue;
        float4 z = make_float4(0.f, 0.f, 0.f, 0.f);
        if (c < 27) {                        // row consumer: 3x-replicated f -> Wsum
            const float* cp = cnt[0][c / 3];
            #pragma unroll
            for (int e = 0; e < 9; e++) {
                float fv = cp[e];
                float4 w = __ldg((const float4*)(g_Wsum + e * 128) + lane);
                z.x = fmaf(fv, w.x, z.x); z.y = fmaf(fv, w.y, z.y);
                z.z = fmaf(fv, w.z, z.z); z.w = fmaf(fv, w.w, z.w);
            }
        } else if (c < 54) {                 // column consumer: 3 distinct groups
            int g0 = 3 * ((c - 27) % 3);
            #pragma unroll
            for (int blk = 0; blk < 3; blk++) {
                const float* cp = cnt[1][g0 + blk];
                #pragma unroll
                for (int e = 0; e < 9; e++) {
                    float fv = cp[e];
                    float4 w = __ldg((const float4*)(g_W1p + (9 * blk + e) * 128) + lane);
                    z.x = fmaf(fv, w.x, z.x); z.y = fmaf(fv, w.y, z.y);
                    z.z = fmaf(fv, w.z, z.z); z.w = fmaf(fv, w.w, z.w);
                }
            }
        } else {                             // box consumer: 3x-replicated f -> Wsum
            int u = c - 54;
            const float* cp = cnt[2][3 * (u / 9) + u % 3];
            #pragma unroll
            for (int e = 0; e < 9; e++) {
                float fv = cp[e];
                float4 w = __ldg((const float4*)(g_Wsum + e * 128) + lane);
                z.x = fmaf(fv, w.x, z.x); z.y = fmaf(fv, w.y, z.y);
                z.z = fmaf(fv, w.z, z.z); z.w = fmaf(fv, w.w, z.w);
            }
        }
        *((float4*)(zs + c * 128) + lane) = z;
        compute_y(c, z);
    }

    // Sequential fill loop: ONE barrier per iteration; selection computed
    // redundantly per-warp with integer redux (positive-float monotone bits).
    for (int iter = 0; iter < 81; ++iter) {
        __syncthreads();   // orders prior score_s/pos_s writes + emptyb[m] clear

        float s0 = score_s[lane];
        float s1 = score_s[lane + 32];
        float s2 = score_s[lane + 64];      // padded region (>=81) reads 0
        unsigned bb = __float_as_uint(s0); int bi = lane;
        unsigned v1 = __float_as_uint(s1); if (v1 > bb) { bb = v1; bi = lane + 32; }
        unsigned v2 = __float_as_uint(s2); if (v2 > bb) { bb = v2; bi = lane + 64; }
        unsigned wmax = redux_maxu(bb);
        if (wmax == 0u) break;              // uniform across all warps
        unsigned cand = (bb == wmax) ? (unsigned)bi : 0xFFu;
        const int m = (int)redux_minu(cand);   // global first-max index
        const int d = pos_s[m];
        if (tid == 0) { emptyb[m] = 0; score_s[m] = 0.f; }

        const int rm = m / 9, cm = m % 9;
        const int cm3 = cm / 3, brm = (rm / 3) * 3;

        const float4 wsum4 = __ldg((const float4*)(g_Wsum + d * 128) + lane);
        const float4 wcol4 = __ldg((const float4*)(g_W1p + (9 * (cm % 3) + d) * 128) + lane);

        for (int i = wid; i < 15; i += 5) {
            int c; float4 w;
            if (i < 3)       { c = 3 * rm + i;                      w = wsum4; }
            else if (i < 12) { c = 27 + 3 * (i - 3) + cm3;          w = wcol4; }
            else             { c = 54 + 3 * (brm + (i - 12)) + cm3; w = wsum4; }
            if (c == m || !emptyb[c]) continue;   // c==m first: race-free vs clear
            float4* zp = (float4*)(zs + c * 128) + lane;
            float4 z = *zp;
            z.x += w.x; z.y += w.y; z.z += w.z; z.w += w.w;
            *zp = z;
            compute_y(c, z);
        }
    }
}

} // namespace

extern "C" void kernel_launch(void* const* d_in, const int* in_sizes, int n_in,
                              void* d_out, int out_size) {
    const float* x  = (const float*)d_in[0];
    const float* W1 = (const float*)d_in[1];
    const float* W2 = (const float*)d_in[2];
    float* out = (float*)d_out;
    int B = in_sizes[0] / 729;
    prep_kernel<<<1, 128>>>(W1);
    sudoku_kernel<<<B, THREADS>>>(x, W2, out);
}